// round 8
// baseline (speedup 1.0000x reference)
#include <cuda_runtime.h>
#include <cuda_bf16.h>
#include <cstddef>

// 3-level periodic db4 analysis DWT, fused in one kernel.
//
// Per level (N even, L=8, filters given already reversed):
//   lo[n] = sum_l h0[l] * x[(2n + l - 3) mod N]
//   hi[n] = sum_l h1[l] * x[(2n + l - 3) mod N]
//
// x: (16,64,65536) fp32 -> 1024 rows of N=65536.
// Output layout (tuple flattened in order):
//   [lo3 : 1024*8192][hi1 : 1024*32768][hi2 : 1024*16384][hi3 : 1024*8192]

#define ROWS      1024
#define N0        65536
#define CHUNKS    8            // per row; each chunk = 8192 input samples
#define THREADS   256

// smem window sizes (floats)
#define SX_SZ     8256         // x window:   x[(t0-32 .. t0+8223) mod N0]
#define SL1_SZ    4120         // lo1 window: lo1[t1-12 .. t1+4107]
#define SL2_SZ    2060         // lo2 window: lo2[t2-8  .. t2+2051]

// output offsets (floats)
#define O_LO3     0u
#define O_HI1     8388608u     // 1024*8192
#define O_HI2     41943040u    // O_HI1 + 1024*32768
#define O_HI3     58720256u    // O_HI2 + 1024*16384

__device__ __forceinline__ void load_window16(const float* __restrict__ p, float w[16]) {
    // p is 16B-aligned by construction
    float4 a = reinterpret_cast<const float4*>(p)[0];
    float4 b = reinterpret_cast<const float4*>(p)[1];
    float4 c = reinterpret_cast<const float4*>(p)[2];
    float4 d = reinterpret_cast<const float4*>(p)[3];
    w[0]=a.x;  w[1]=a.y;  w[2]=a.z;  w[3]=a.w;
    w[4]=b.x;  w[5]=b.y;  w[6]=b.z;  w[7]=b.w;
    w[8]=c.x;  w[9]=c.y;  w[10]=c.z; w[11]=c.w;
    w[12]=d.x; w[13]=d.y; w[14]=d.z; w[15]=d.w;
}

// 4 consecutive outputs for both filters from a 16-float window.
// Output e uses taps w[2e+1 .. 2e+8].
__device__ __forceinline__ void conv8x4(const float w[16],
                                        const float f0[8], const float f1[8],
                                        float4& lo, float4& hi) {
    float a[4], b[4];
#pragma unroll
    for (int e = 0; e < 4; ++e) {
        float s0 = 0.f, s1 = 0.f;
#pragma unroll
        for (int l = 0; l < 8; ++l) {
            float v = w[2*e + 1 + l];
            s0 = fmaf(f0[l], v, s0);
            s1 = fmaf(f1[l], v, s1);
        }
        a[e] = s0; b[e] = s1;
    }
    lo = make_float4(a[0], a[1], a[2], a[3]);
    hi = make_float4(b[0], b[1], b[2], b[3]);
}

extern "C" __global__ void __launch_bounds__(THREADS, 3)
dwt3_db4_kernel(const float* __restrict__ x,
                const float* __restrict__ h0,
                const float* __restrict__ h1,
                float* __restrict__ out) {
    extern __shared__ float sm[];
    float* sx  = sm;                       // SX_SZ
    float* sl1 = sm + SX_SZ;               // SL1_SZ  (16B-aligned: 8256*4 % 16 == 0)
    float* sl2 = sm + SX_SZ + SL1_SZ;      // SL2_SZ  (16B-aligned)

    const int row = blockIdx.y;
    const int c   = blockIdx.x;
    const int tid = threadIdx.x;

    const int t1 = c << 12;   // lvl1 output base (per-row, N1=32768)
    const int t2 = c << 11;   // lvl2 output base (N2=16384)
    const int t3 = c << 10;   // lvl3 output base (N3=8192)

    // filters -> registers (broadcast, L1-hit)
    float f0[8], f1[8];
#pragma unroll
    for (int l = 0; l < 8; ++l) { f0[l] = __ldg(h0 + l); f1[l] = __ldg(h1 + l); }

    // ---- stage 0: load x window sx[i] = x[(t0 - 32 + i) & 65535] ----
    {
        const float4* x4 = reinterpret_cast<const float4*>(x + (size_t)row * N0);
        float4* sx4 = reinterpret_cast<float4*>(sx);
        const int base4 = (c << 11) - 8;   // (t0 - 32)/4
#pragma unroll 2
        for (int i = tid; i < SX_SZ / 4; i += THREADS) {
            sx4[i] = __ldg(x4 + ((base4 + i) & (N0/4 - 1)));
        }
    }
    __syncthreads();

    // ---- stage 1: sl1[j] = lo1[t1 - 12 + j], j in [0,4120); hi1 -> gmem ----
    // tap: x[2m+l-3] with m = t1-12+j  ->  sx[2j + l + 5]  ->  window base sx + 2*j0 + 4
    {
        float* hi1 = out + O_HI1 + (size_t)row * 32768 + (t1 - 12);
        for (int g = tid; g < 1030; g += THREADS) {
            const int j0 = g << 2;
            float w[16];
            load_window16(sx + 2*j0 + 4, w);
            float4 lo, hi;
            conv8x4(w, f0, f1, lo, hi);
            reinterpret_cast<float4*>(sl1 + j0)[0] = lo;
            if (j0 >= 12 && j0 <= 4104)
                reinterpret_cast<float4*>(hi1 + j0)[0] = hi;
        }
    }
    __syncthreads();

    // ---- stage 2: sl2[k] = lo2[t2 - 8 + k], k in [4,2060); hi2 -> gmem ----
    // tap: lo1[2m2+l-3] with m2 = t2-8+k  ->  sl1[2k + l - 7]  ->  window base sl1 + 2*k0 - 8
    {
        float* hi2 = out + O_HI2 + (size_t)row * 16384 + (t2 - 8);
        for (int g = tid; g < 514; g += THREADS) {
            const int k0 = (g << 2) + 4;
            float w[16];
            load_window16(sl1 + 2*k0 - 8, w);
            float4 lo, hi;
            conv8x4(w, f0, f1, lo, hi);
            reinterpret_cast<float4*>(sl2 + k0)[0] = lo;
            if (k0 >= 8 && k0 <= 2052)
                reinterpret_cast<float4*>(hi2 + k0)[0] = hi;
        }
    }
    __syncthreads();

    // ---- stage 3: lo3/hi3 -> gmem, v in [0,1024), one group of 4 per thread ----
    // tap: lo2[2n+l-3] with n = t3+v  ->  sl2[2v + l + 5]  ->  window base sl2 + 2*v0 + 4
    {
        float* lo3 = out + O_LO3 + (size_t)row * 8192 + t3;
        float* hi3 = out + O_HI3 + (size_t)row * 8192 + t3;
        const int v0 = tid << 2;
        float w[16];
        load_window16(sl2 + 2*v0 + 4, w);
        float4 lo, hi;
        conv8x4(w, f0, f1, lo, hi);
        reinterpret_cast<float4*>(lo3 + v0)[0] = lo;
        reinterpret_cast<float4*>(hi3 + v0)[0] = hi;
    }
}

extern "C" void kernel_launch(void* const* d_in, const int* in_sizes, int n_in,
                              void* d_out, int out_size) {
    const float* x  = (const float*)d_in[0];
    const float* h0 = (const float*)d_in[1];
    const float* h1 = (const float*)d_in[2];
    float* out = (float*)d_out;

    const size_t smem = (size_t)(SX_SZ + SL1_SZ + SL2_SZ) * sizeof(float); // 57744 B
    cudaFuncSetAttribute(dwt3_db4_kernel,
                         cudaFuncAttributeMaxDynamicSharedMemorySize, (int)smem);

    dim3 grid(CHUNKS, ROWS);
    dwt3_db4_kernel<<<grid, THREADS, smem>>>(x, h0, h1, out);
}

// round 9
// speedup vs baseline: 1.2204x; 1.2204x over previous
#include <cuda_runtime.h>
#include <cuda_bf16.h>
#include <cstddef>

// 3-level periodic db4 analysis DWT, fused in one kernel.
//
// Per level (N even, L=8, filters given already reversed):
//   lo[n] = sum_l h0[l] * x[(2n + l - 3) mod N]
//   hi[n] = sum_l h1[l] * x[(2n + l - 3) mod N]
//
// x: (16,64,65536) fp32 -> 1024 rows of N=65536.
// Output layout: [lo3 : 1024*8192][hi1 : 1024*32768][hi2 : 1024*16384][hi3 : 1024*8192]
//
// R9 changes vs R8:
//  * chunk 8192 -> 4096: smem 57.7KB -> 29.1KB, 3 -> 5 CTAs/SM
//  * XOR bank swizzle (q ^= (q>>3)&1 on float4 index) kills the 2-way LDS
//    conflicts caused by the 32B/lane window stride.

#define ROWS      1024
#define N0        65536
#define CHUNKS    16           // per row; each chunk = 4096 input samples
#define THREADS   256

// smem region sizes (floats); each region base is 128B-aligned (quads % 8 == 0)
#define SX_SZ     4160         // x window:   x[(t0-32 .. t0+4127) mod N0]   (1040 quads)
#define SL1_SZ    2080         // lo1 window: lo1[t1-12 .. t1+2059] (+pad)   (520 quads)
#define SL2_SZ    1036         // lo2 window: lo2[t2-8  .. t2+1027]          (259 quads)

// output offsets (floats)
#define O_LO3     0u
#define O_HI1     8388608u     // 1024*8192
#define O_HI2     41943040u    // O_HI1 + 1024*32768
#define O_HI3     58720256u    // O_HI2 + 1024*16384

// Bank swizzle on float4 (16B) index: lanes that would collide within an
// 8-lane LDS.128 phase differ by 8 quads (bit3); fold bit3 into bit0.
__device__ __forceinline__ int sw(int q) { return q ^ ((q >> 3) & 1); }

__device__ __forceinline__ void load4q(const float4* __restrict__ b, int q, float w[16]) {
    float4 a = b[sw(q)];
    float4 c = b[sw(q + 1)];
    float4 d = b[sw(q + 2)];
    float4 e = b[sw(q + 3)];
    w[0]=a.x;  w[1]=a.y;  w[2]=a.z;  w[3]=a.w;
    w[4]=c.x;  w[5]=c.y;  w[6]=c.z;  w[7]=c.w;
    w[8]=d.x;  w[9]=d.y;  w[10]=d.z; w[11]=d.w;
    w[12]=e.x; w[13]=e.y; w[14]=e.z; w[15]=e.w;
}

__device__ __forceinline__ void load3q(const float4* __restrict__ b, int q, float w[12]) {
    float4 a = b[sw(q)];
    float4 c = b[sw(q + 1)];
    float4 d = b[sw(q + 2)];
    w[0]=a.x; w[1]=a.y; w[2]=a.z;  w[3]=a.w;
    w[4]=c.x; w[5]=c.y; w[6]=c.z;  w[7]=c.w;
    w[8]=d.x; w[9]=d.y; w[10]=d.z; w[11]=d.w;
}

// 4 consecutive outputs for both filters; output e uses taps w[2e+1 .. 2e+8].
__device__ __forceinline__ void conv8x4(const float w[16],
                                        const float f0[8], const float f1[8],
                                        float4& lo, float4& hi) {
    float a[4], b[4];
#pragma unroll
    for (int e = 0; e < 4; ++e) {
        float s0 = 0.f, s1 = 0.f;
#pragma unroll
        for (int l = 0; l < 8; ++l) {
            float v = w[2*e + 1 + l];
            s0 = fmaf(f0[l], v, s0);
            s1 = fmaf(f1[l], v, s1);
        }
        a[e] = s0; b[e] = s1;
    }
    lo = make_float4(a[0], a[1], a[2], a[3]);
    hi = make_float4(b[0], b[1], b[2], b[3]);
}

// 2 consecutive outputs; output e uses taps w[2e+1 .. 2e+8].
__device__ __forceinline__ void conv8x2(const float w[12],
                                        const float f0[8], const float f1[8],
                                        float2& lo, float2& hi) {
    float a[2], b[2];
#pragma unroll
    for (int e = 0; e < 2; ++e) {
        float s0 = 0.f, s1 = 0.f;
#pragma unroll
        for (int l = 0; l < 8; ++l) {
            float v = w[2*e + 1 + l];
            s0 = fmaf(f0[l], v, s0);
            s1 = fmaf(f1[l], v, s1);
        }
        a[e] = s0; b[e] = s1;
    }
    lo = make_float2(a[0], a[1]);
    hi = make_float2(b[0], b[1]);
}

extern "C" __global__ void __launch_bounds__(THREADS, 5)
dwt3_db4_kernel(const float* __restrict__ x,
                const float* __restrict__ h0,
                const float* __restrict__ h1,
                float* __restrict__ out) {
    extern __shared__ float sm[];
    float4* sx4  = reinterpret_cast<float4*>(sm);                      // 1040 quads
    float4* sl14 = reinterpret_cast<float4*>(sm + SX_SZ);              // 520 quads
    float4* sl24 = reinterpret_cast<float4*>(sm + SX_SZ + SL1_SZ);     // 259 quads

    const int row = blockIdx.y;
    const int c   = blockIdx.x;
    const int tid = threadIdx.x;

    const int t1 = c << 11;   // lvl1 output base (N1=32768), 2048 per chunk
    const int t2 = c << 10;   // lvl2 output base (N2=16384), 1024 per chunk
    const int t3 = c << 9;    // lvl3 output base (N3=8192),   512 per chunk

    float f0[8], f1[8];
#pragma unroll
    for (int l = 0; l < 8; ++l) { f0[l] = __ldg(h0 + l); f1[l] = __ldg(h1 + l); }

    // ---- stage 0: sx[i] = x[(t0 - 32 + i) & 65535], SX_SZ floats ----
    {
        const float4* x4 = reinterpret_cast<const float4*>(x + (size_t)row * N0);
        const int base4 = (c << 10) - 8;   // (t0 - 32)/4
#pragma unroll 2
        for (int i = tid; i < SX_SZ / 4; i += THREADS) {
            sx4[sw(i)] = __ldg(x4 + ((base4 + i) & (N0/4 - 1)));
        }
    }
    __syncthreads();

    // ---- stage 1: sl1[j] = lo1[t1-12+j], j in [0,2072); hi1 -> gmem ----
    // tap: x[2m+l-3], m = t1-12+j  ->  sx[2j+l+5]; group j0=4g -> window quad 2g+1
    {
        float* hi1 = out + O_HI1 + (size_t)row * 32768 + (t1 - 12);
        for (int g = tid; g < 518; g += THREADS) {
            const int j0 = g << 2;
            float w[16];
            load4q(sx4, 2*g + 1, w);
            float4 lo, hi;
            conv8x4(w, f0, f1, lo, hi);
            sl14[sw(g)] = lo;
            if (j0 >= 12 && j0 <= 2056)
                reinterpret_cast<float4*>(hi1 + j0)[0] = hi;
        }
    }
    __syncthreads();

    // ---- stage 2: sl2[k] = lo2[t2-8+k], k in [4,1036); hi2 -> gmem ----
    // tap: lo1[2m2+l-3], m2 = t2-8+k  ->  sl1[2k+l-7]; group k0=4g+4 -> window quad 2g
    {
        float* hi2 = out + O_HI2 + (size_t)row * 16384 + (t2 - 8);
        for (int g = tid; g < 258; g += THREADS) {
            const int k0 = (g << 2) + 4;
            float w[16];
            load4q(sl14, 2*g, w);
            float4 lo, hi;
            conv8x4(w, f0, f1, lo, hi);
            sl24[sw(g + 1)] = lo;
            if (k0 >= 8 && k0 <= 1028)
                reinterpret_cast<float4*>(hi2 + k0)[0] = hi;
        }
    }
    __syncthreads();

    // ---- stage 3: lo3/hi3 -> gmem, v in [0,512), 2 outputs/thread ----
    // tap: lo2[2n+l-3], n = t3+v  ->  sl2[2v+l+5]; v0=2*tid -> window quad tid+1
    {
        float* lo3 = out + O_LO3 + (size_t)row * 8192 + t3;
        float* hi3 = out + O_HI3 + (size_t)row * 8192 + t3;
        const int v0 = tid << 1;
        float w[12];
        load3q(sl24, tid + 1, w);
        float2 lo, hi;
        conv8x2(w, f0, f1, lo, hi);
        reinterpret_cast<float2*>(lo3 + v0)[0] = lo;
        reinterpret_cast<float2*>(hi3 + v0)[0] = hi;
    }
}

extern "C" void kernel_launch(void* const* d_in, const int* in_sizes, int n_in,
                              void* d_out, int out_size) {
    const float* x  = (const float*)d_in[0];
    const float* h0 = (const float*)d_in[1];
    const float* h1 = (const float*)d_in[2];
    float* out = (float*)d_out;

    const size_t smem = (size_t)(SX_SZ + SL1_SZ + SL2_SZ) * sizeof(float); // 29104 B
    cudaFuncSetAttribute(dwt3_db4_kernel,
                         cudaFuncAttributeMaxDynamicSharedMemorySize, (int)smem);

    dim3 grid(CHUNKS, ROWS);
    dwt3_db4_kernel<<<grid, THREADS, smem>>>(x, h0, h1, out);
}